// round 16
// baseline (speedup 1.0000x reference)
#include <cuda_runtime.h>
#include <cstdint>

// CF_spikes -- scalar-order fp32, packed FFMA2 (fma.rn.f32x2).
// Each f32x2 half is an independent RN FMA -> per-(b,h,t) chain is bitwise
// identical to the passing R14 kernel (rel_err 7.543161e-04).
// R14 was fma-pipe bound (64 FFMA/thread/jc); packing t in pairs halves
// fma-pipe ops: 32 FFMA2/thread/jc.

constexpr int kIN = 784, kH1 = 128, kH2 = 64, kOUT = 10, kT = 16;
constexpr int kNCH = 49;                    // 49 j-chunks of 16
constexpr int SSTR = 272;                   // bytes per (j,b) s-slot

// dynamic SMEM map
constexpr int OFF_S  = 0;                   // s floats: 256 slots * 272B = 69632
constexpr int OFF_W1 = 69632;               // W1T chunk dbl buf: 2 * 8192
constexpr int OFF_W2 = 86016;               // W2T padded: 128 * 272 = 34816
constexpr int OFF_S1 = 120832;              // s1 [16b][128h] u16 = 4096
constexpr int OFF_S2 = 124928;              // s2 [16b][64h2] u16 = 2048
constexpr unsigned DYN_SZ = 127232;

__device__ __align__(16) unsigned short g_mask[(long long)32768 * kIN];
__device__ __align__(16) float g_W1T[kIN * kH1];   // [j][h]
__device__ __align__(16) float g_W2T[kH1 * kH2];   // [hh][h2]

__device__ __forceinline__ uint32_t smem_u32(const void* p) {
    uint32_t a;
    asm("{ .reg .u64 t; cvta.to.shared.u64 t, %1; cvt.u32.u64 %0, t; }" : "=r"(a) : "l"(p));
    return a;
}
#define CP16(d, s) asm volatile("cp.async.cg.shared.global [%0], [%1], 16;" :: "r"(d), "l"(s) : "memory")
#define CPC()      asm volatile("cp.async.commit_group;" ::: "memory")
#define CPW1()     asm volatile("cp.async.wait_group 1;" ::: "memory")
#define CPW0()     asm volatile("cp.async.wait_group 0;" ::: "memory")
// packed dual-RN FMA: d.lo += a.lo*b.lo ; d.hi += a.hi*b.hi (each bitwise RN)
#define FMA2(d, a, b) asm("fma.rn.f32x2 %0, %1, %2, %0;" : "+l"(d) : "l"(a), "l"(b))
#define PACK2(o, f)   asm("mov.b64 %0, {%1, %1};" : "=l"(o) : "f"(f))
#define UNPK2(lo, hi, p) asm("mov.b64 {%0, %1}, %2;" : "=f"(lo), "=f"(hi) : "l"(p))

// ---------------------------------------------------------------------------
__global__ void k_prep(const float* __restrict__ W1, const float* __restrict__ W2) {
    int idx = blockIdx.x * 256 + threadIdx.x;
    if (idx < kIN * kH1) {
        int j = idx >> 7, h = idx & 127;
        g_W1T[idx] = W1[h * kIN + j];
    } else if (idx < kIN * kH1 + kH1 * kH2) {
        int i2 = idx - kIN * kH1;
        int hh = i2 >> 6, h2 = i2 & 63;
        g_W2T[i2] = W2[h2 * kH1 + hh];
    }
}

// bit-exact encoder masks
__global__ void k_encode(const float* __restrict__ feat, int B) {
    long long idx = (long long)blockIdx.x * 256 + threadIdx.x;
    if (idx >= (long long)B * kIN) return;
    float f = feat[idx], a = 0.0f;
    unsigned m = 0;
    #pragma unroll
    for (int t = 0; t < kT; t++) {
        a += f;
        if (a >= 1.0f) { m |= (1u << t); a -= 1.0f; }
    }
    g_mask[idx] = (unsigned short)m;
}

// expand one mask word -> 16 {0,1} floats at SMEM slot
__device__ __forceinline__ void expand16(char* sp, unsigned m) {
    #pragma unroll
    for (int t4 = 0; t4 < 4; t4++) {
        float4 v;
        v.x = __uint_as_float(((m >> (t4 * 4 + 0)) & 1u) * 0x3F800000u);
        v.y = __uint_as_float(((m >> (t4 * 4 + 1)) & 1u) * 0x3F800000u);
        v.z = __uint_as_float(((m >> (t4 * 4 + 2)) & 1u) * 0x3F800000u);
        v.w = __uint_as_float(((m >> (t4 * 4 + 3)) & 1u) * 0x3F800000u);
        *reinterpret_cast<float4*>(sp + t4 * 16) = v;
    }
}

// ---------------------------------------------------------------------------
// k_main: 16 batch rows/CTA, 2048 CTAs, 512 threads.
// Layer 1: thread owns (4 h, 1 b); U packed as 4x8 f32x2 over t-pairs.
// Layer 2: thread owns (2 h2, 1 b); all 512 threads compute.
// ---------------------------------------------------------------------------
__global__ void __launch_bounds__(512, 1)
k_main(const float* __restrict__ b1, const float* __restrict__ b2,
       const float* __restrict__ W3, const float* __restrict__ b3,
       const float* __restrict__ scale, float* __restrict__ out)
{
    extern __shared__ char dsm[];
    const uint32_t sb = smem_u32(dsm);
    const int tid = threadIdx.x;
    const int b = tid & 15, hg = tid >> 4;       // hg 0..31
    const long long row0 = (long long)blockIdx.x * 16;

    // stage W2T (padded rows 272B) + first W1T chunk, one cp.async group
    for (int i = tid; i < 2048; i += 512) {
        int r = i >> 4, g = i & 15;
        CP16(sb + OFF_W2 + (uint32_t)(r * SSTR + g * 16),
             (const char*)(g_W2T + r * kH2) + g * 16);
    }
    CP16(sb + OFF_W1 + (uint32_t)(tid * 16), (const char*)g_W1T + tid * 16);
    CPC();

    // ================= Layer 1 =================
    unsigned long long U2[4][8];                 // [h][t-pair], (t even, t odd)
    #pragma unroll
    for (int h = 0; h < 4; h++)
        #pragma unroll
        for (int p = 0; p < 8; p++) U2[h][p] = 0ULL;

    for (int c = 0; c < kNCH; c++) {
        __syncthreads();                          // prev chunk fully consumed
        if (tid < 256) {                          // expand s for this chunk
            int jc = tid >> 4, bb = tid & 15;
            unsigned m = g_mask[(row0 + bb) * kIN + c * 16 + jc];
            expand16(dsm + OFF_S + (jc * 16 + bb) * SSTR, m);
        }
        if (c + 1 < kNCH) {                       // prefetch next W1T chunk
            CP16(sb + OFF_W1 + (uint32_t)(((c + 1) & 1) * 8192 + tid * 16),
                 (const char*)(g_W1T + (c + 1) * 2048) + tid * 16);
            CPC(); CPW1();
        } else { CPW0(); }
        __syncthreads();                          // s + w visible

        const char* wb = dsm + OFF_W1 + (c & 1) * 8192;
        #pragma unroll
        for (int jc = 0; jc < 16; jc++) {
            float4 w4 = *reinterpret_cast<const float4*>(wb + jc * 512 + hg * 16);
            unsigned long long ww[4];
            PACK2(ww[0], w4.x); PACK2(ww[1], w4.y);
            PACK2(ww[2], w4.z); PACK2(ww[3], w4.w);
            const ulonglong2* sp2 = reinterpret_cast<const ulonglong2*>(
                dsm + OFF_S + (jc * 16 + b) * SSTR);
            ulonglong2 q0 = sp2[0], q1 = sp2[1], q2 = sp2[2], q3 = sp2[3];
            unsigned long long sv[8] = {q0.x, q0.y, q1.x, q1.y,
                                        q2.x, q2.y, q3.x, q3.y};
            #pragma unroll
            for (int h = 0; h < 4; h++)
                #pragma unroll
                for (int p = 0; p < 8; p++)
                    FMA2(U2[h][p], ww[h], sv[p]);
        }
    }

    // ---- layer-1 dynamics in-register (bit-exact: v=(v+U)+bb) -> s1 ----
    unsigned short* s1 = (unsigned short*)(dsm + OFF_S1);
    #pragma unroll
    for (int hh = 0; hh < 4; hh++) {
        int h = hg * 4 + hh;
        float bbv = b1[h], v = 0.0f; unsigned s = 0;
        #pragma unroll
        for (int p = 0; p < 8; p++) {
            float lo, hi;
            UNPK2(lo, hi, U2[hh][p]);
            v = (v + lo) + bbv;
            if (v >= 1.0f) { s |= (1u << (2 * p));     v -= 1.0f; }
            v = (v + hi) + bbv;
            if (v >= 1.0f) { s |= (1u << (2 * p + 1)); v -= 1.0f; }
        }
        s1[b * kH1 + h] = (unsigned short)s;
    }
    __syncthreads();

    // ================= Layer 2 (all 512 threads: 2 h2 x 1 b each) ===========
    unsigned long long V2[2][8];
    #pragma unroll
    for (int h = 0; h < 2; h++)
        #pragma unroll
        for (int p = 0; p < 8; p++) V2[h][p] = 0ULL;

    for (int c2 = 0; c2 < 8; c2++) {
        __syncthreads();
        if (tid < 256) {
            int jc = tid >> 4, bb = tid & 15;
            unsigned m = s1[bb * kH1 + c2 * 16 + jc];
            expand16(dsm + OFF_S + (jc * 16 + bb) * SSTR, m);
        }
        __syncthreads();
        #pragma unroll
        for (int jc = 0; jc < 16; jc++) {
            float2 w2 = *reinterpret_cast<const float2*>(
                dsm + OFF_W2 + (c2 * 16 + jc) * SSTR + hg * 8);
            unsigned long long ww0, ww1;
            PACK2(ww0, w2.x); PACK2(ww1, w2.y);
            const ulonglong2* sp2 = reinterpret_cast<const ulonglong2*>(
                dsm + OFF_S + (jc * 16 + b) * SSTR);
            ulonglong2 q0 = sp2[0], q1 = sp2[1], q2 = sp2[2], q3 = sp2[3];
            unsigned long long sv[8] = {q0.x, q0.y, q1.x, q1.y,
                                        q2.x, q2.y, q3.x, q3.y};
            #pragma unroll
            for (int p = 0; p < 8; p++) {
                FMA2(V2[0][p], ww0, sv[p]);
                FMA2(V2[1][p], ww1, sv[p]);
            }
        }
    }

    // ---- layer-2 dynamics -> s2 ----
    unsigned short* s2 = (unsigned short*)(dsm + OFF_S2);
    #pragma unroll
    for (int hh = 0; hh < 2; hh++) {
        int h2 = hg * 2 + hh;
        float bbv = b2[h2], v = 0.0f; unsigned s = 0;
        #pragma unroll
        for (int p = 0; p < 8; p++) {
            float lo, hi;
            UNPK2(lo, hi, V2[hh][p]);
            v = (v + lo) + bbv;
            if (v >= 1.0f) { s |= (1u << (2 * p));     v -= 1.0f; }
            v = (v + hi) + bbv;
            if (v >= 1.0f) { s |= (1u << (2 * p + 1)); v -= 1.0f; }
        }
        s2[b * kH2 + h2] = (unsigned short)s;
    }
    __syncthreads();

    // ================= Layer 3 + output (scalar, hh ascending) ==============
    if (tid < kOUT * 16) {
        int o = tid >> 4, rr = tid & 15;
        float a3[kT];
        #pragma unroll
        for (int t = 0; t < kT; t++) a3[t] = 0.0f;
        const float* w3p = W3 + o * kH2;
        for (int hh = 0; hh < kH2; hh++) {
            float w = w3p[hh]; unsigned m = s2[rr * kH2 + hh];
            #pragma unroll
            for (int t = 0; t < kT; t++)
                if (m & (1u << t)) a3[t] += w;
        }
        float v = 0.0f; int cnt = 0; float bbv = b3[o];
        #pragma unroll
        for (int t = 0; t < kT; t++) {
            v = (v + a3[t]) + bbv;
            if (v >= 1.0f) { cnt++; v -= 1.0f; }
        }
        out[(row0 + rr) * kOUT + o] = ((float)cnt * (1.0f / 16.0f)) * scale[o];
    }
}

// ---------------------------------------------------------------------------
extern "C" void kernel_launch(void* const* d_in, const int* in_sizes, int n_in,
                              void* d_out, int out_size)
{
    const float* feat  = (const float*)d_in[0];
    const float* W1    = (const float*)d_in[1];
    const float* b1    = (const float*)d_in[2];
    const float* W2    = (const float*)d_in[3];
    const float* b2    = (const float*)d_in[4];
    const float* W3    = (const float*)d_in[5];
    const float* b3    = (const float*)d_in[6];
    const float* scale = (const float*)d_in[7];
    float*       out   = (float*)d_out;

    const int B = in_sizes[0] / kIN;   // 32768

    cudaFuncSetAttribute(k_main, cudaFuncAttributeMaxDynamicSharedMemorySize, DYN_SZ);

    int nprep = kIN * kH1 + kH1 * kH2;
    k_prep<<<(nprep + 255) / 256, 256>>>(W1, W2);
    k_encode<<<(unsigned)(((long long)B * kIN + 255) / 256), 256>>>(feat, B);
    k_main<<<B / 16, 512, DYN_SZ>>>(b1, b2, W3, b3, scale, out);
}

// round 17
// speedup vs baseline: 1.0023x; 1.0023x over previous
#include <cuda_runtime.h>
#include <cstdint>

// CF_spikes -- scalar-order fp32 via PREDICATED FADD (@P FADD U,U,w).
// Chain is bitwise identical to the passing kernels (rel_err 7.543161e-04):
//   taken: U = RN(U + w)  ==  fmaf(w, 1.0f, U);  not-taken: U unchanged.
// Why faster than FFMA: FFMA w,s,U has 3 distinct GPRs -> RF-bank rt=2/SMSP.
// FADD U,U,w has 2 distinct GPRs -> banking 1+1 -> rt=1 (cf. FFMA-imm rt=1).
// One LOP3->P predicate per (b,t,j), shared by the 4 h-adds (alu pipe).
// Mask bits consumed directly; the float-expansion stage is deleted.

constexpr int kIN = 784, kH1 = 128, kH2 = 64, kOUT = 10, kT = 16;
constexpr int kNCH = 49;                    // 49 j-chunks of 16

// dynamic SMEM map
constexpr int OFF_M  = 0;                   // masks [16b][8 u32] = 512B
constexpr int OFF_W1 = 1024;                // W1T chunk dbl buf 2*8192 -> 17408
constexpr int OFF_W2 = 17408;               // W2T [128hh][64h2] f32 = 32768 -> 50176
constexpr int OFF_S1 = 50176;               // s1 [16b][128h] u16 = 4096 -> 54272
constexpr int OFF_S2 = 54272;               // s2 [16b][64h2] u16 = 2048 -> 56320
constexpr unsigned DYN_SZ = 57344;

__device__ __align__(16) unsigned short g_mask[(long long)32768 * kIN];
__device__ __align__(16) float g_W1T[kIN * kH1];   // [j][h]
__device__ __align__(16) float g_W2T[kH1 * kH2];   // [hh][h2]

__device__ __forceinline__ uint32_t smem_u32(const void* p) {
    uint32_t a;
    asm("{ .reg .u64 t; cvta.to.shared.u64 t, %1; cvt.u32.u64 %0, t; }" : "=r"(a) : "l"(p));
    return a;
}
#define CP16(d, s) asm volatile("cp.async.cg.shared.global [%0], [%1], 16;" :: "r"(d), "l"(s) : "memory")
#define CPC()      asm volatile("cp.async.commit_group;" ::: "memory")
#define CPW1()     asm volatile("cp.async.wait_group 1;" ::: "memory")
#define CPW0()     asm volatile("cp.async.wait_group 0;" ::: "memory")

// ---------------------------------------------------------------------------
__global__ void k_prep(const float* __restrict__ W1, const float* __restrict__ W2) {
    int idx = blockIdx.x * 256 + threadIdx.x;
    if (idx < kIN * kH1) {
        int j = idx >> 7, h = idx & 127;
        g_W1T[idx] = W1[h * kIN + j];
    } else if (idx < kIN * kH1 + kH1 * kH2) {
        int i2 = idx - kIN * kH1;
        int hh = i2 >> 6, h2 = i2 & 63;
        g_W2T[i2] = W2[h2 * kH1 + hh];
    }
}

// bit-exact encoder masks
__global__ void k_encode(const float* __restrict__ feat, int B) {
    long long idx = (long long)blockIdx.x * 256 + threadIdx.x;
    if (idx >= (long long)B * kIN) return;
    float f = feat[idx], a = 0.0f;
    unsigned m = 0;
    #pragma unroll
    for (int t = 0; t < kT; t++) {
        a += f;
        if (a >= 1.0f) { m |= (1u << t); a -= 1.0f; }
    }
    g_mask[idx] = (unsigned short)m;
}

// ---------------------------------------------------------------------------
// k_main: 16 batch rows/CTA, 2048 CTAs, 512 threads.
// Layer 1: thread owns (4 h, 16 t, 1 b); per j: 1 LOP3->P per t + 4 @P FADD.
// Layer 2: thread owns (2 h2, 16 t, 1 b); same pattern over hh.
// ---------------------------------------------------------------------------
__global__ void __launch_bounds__(512, 1)
k_main(const float* __restrict__ b1, const float* __restrict__ b2,
       const float* __restrict__ W3, const float* __restrict__ b3,
       const float* __restrict__ scale, float* __restrict__ out)
{
    extern __shared__ char dsm[];
    const uint32_t sb = smem_u32(dsm);
    const int tid = threadIdx.x;
    const int b = tid & 15, hg = tid >> 4;       // hg 0..31
    const long long row0 = (long long)blockIdx.x * 16;

    // stage W2T rows ([hh][64] f32) + first W1T chunk, one cp.async group
    for (int i = tid; i < 2048; i += 512) {      // 32KB W2
        CP16(sb + OFF_W2 + (uint32_t)(i * 16), (const char*)g_W2T + i * 16);
    }
    CP16(sb + OFF_W1 + (uint32_t)(tid * 16), (const char*)g_W1T + tid * 16);
    CPC();

    // ================= Layer 1 =================
    float U[4][kT];
    #pragma unroll
    for (int h = 0; h < 4; h++)
        #pragma unroll
        for (int t = 0; t < kT; t++) U[h][t] = 0.0f;

    for (int c = 0; c < kNCH; c++) {
        __syncthreads();                          // prev chunk fully consumed
        if (tid < 128) {                          // stage raw masks: [b][jp] u32
            int bb = tid >> 3, jp = tid & 7;
            *(uint32_t*)(dsm + OFF_M + bb * 32 + jp * 4) =
                *(const uint32_t*)(g_mask + (row0 + bb) * kIN + c * 16 + jp * 2);
        }
        if (c + 1 < kNCH) {                       // prefetch next W1T chunk
            CP16(sb + OFF_W1 + (uint32_t)(((c + 1) & 1) * 8192 + tid * 16),
                 (const char*)(g_W1T + (c + 1) * 2048) + tid * 16);
            CPC(); CPW1();
        } else { CPW0(); }
        __syncthreads();                          // masks + w visible

        const char* wb = dsm + OFF_W1 + (c & 1) * 8192;
        uint4 q0 = *(const uint4*)(dsm + OFF_M + b * 32);
        uint4 q1 = *(const uint4*)(dsm + OFF_M + b * 32 + 16);
        uint32_t qs[8] = {q0.x, q0.y, q0.z, q0.w, q1.x, q1.y, q1.z, q1.w};

        #pragma unroll
        for (int jp = 0; jp < 8; jp++) {          // j pair: bits 0..15 / 16..31
            float4 w0 = *(const float4*)(wb + (jp * 2) * 512 + hg * 16);
            float4 w1 = *(const float4*)(wb + (jp * 2 + 1) * 512 + hg * 16);
            uint32_t q = qs[jp];
            #pragma unroll
            for (int t = 0; t < kT; t++) {
                if (q & (1u << t)) {              // j even first (ascending j)
                    U[0][t] += w0.x; U[1][t] += w0.y;
                    U[2][t] += w0.z; U[3][t] += w0.w;
                }
                if (q & (0x10000u << t)) {
                    U[0][t] += w1.x; U[1][t] += w1.y;
                    U[2][t] += w1.z; U[3][t] += w1.w;
                }
            }
        }
    }

    // ---- layer-1 dynamics in-register (bit-exact: v=(v+U)+bb) -> s1 ----
    unsigned short* s1 = (unsigned short*)(dsm + OFF_S1);
    #pragma unroll
    for (int hh = 0; hh < 4; hh++) {
        int h = hg * 4 + hh;
        float bbv = b1[h], v = 0.0f; unsigned s = 0;
        #pragma unroll
        for (int t = 0; t < kT; t++) {
            v = (v + U[hh][t]) + bbv;
            if (v >= 1.0f) { s |= (1u << t); v -= 1.0f; }
        }
        s1[b * kH1 + h] = (unsigned short)s;
    }
    __syncthreads();

    // ================= Layer 2: thread owns (2 h2, 16 t, 1 b) ==============
    float V[2][kT];
    #pragma unroll
    for (int h = 0; h < 2; h++)
        #pragma unroll
        for (int t = 0; t < kT; t++) V[h][t] = 0.0f;

    #pragma unroll 8
    for (int hhp = 0; hhp < 64; hhp++) {          // hh pair (even, odd)
        uint32_t q = *(const uint32_t*)(s1 + b * kH1 + hhp * 2);
        float2 wA = *(const float2*)(dsm + OFF_W2 + (hhp * 2) * 256 + hg * 8);
        float2 wB = *(const float2*)(dsm + OFF_W2 + (hhp * 2 + 1) * 256 + hg * 8);
        #pragma unroll
        for (int t = 0; t < kT; t++) {
            if (q & (1u << t))       { V[0][t] += wA.x; V[1][t] += wA.y; }
            if (q & (0x10000u << t)) { V[0][t] += wB.x; V[1][t] += wB.y; }
        }
    }

    // ---- layer-2 dynamics -> s2 ----
    unsigned short* s2 = (unsigned short*)(dsm + OFF_S2);
    #pragma unroll
    for (int hh = 0; hh < 2; hh++) {
        int h2 = hg * 2 + hh;
        float bbv = b2[h2], v = 0.0f; unsigned s = 0;
        #pragma unroll
        for (int t = 0; t < kT; t++) {
            v = (v + V[hh][t]) + bbv;
            if (v >= 1.0f) { s |= (1u << t); v -= 1.0f; }
        }
        s2[b * kH2 + h2] = (unsigned short)s;
    }
    __syncthreads();

    // ================= Layer 3 + output (scalar, hh ascending) ==============
    if (tid < kOUT * 16) {
        int o = tid >> 4, rr = tid & 15;
        float a3[kT];
        #pragma unroll
        for (int t = 0; t < kT; t++) a3[t] = 0.0f;
        const float* w3p = W3 + o * kH2;
        for (int hh = 0; hh < kH2; hh++) {
            float w = w3p[hh]; unsigned m = s2[rr * kH2 + hh];
            #pragma unroll
            for (int t = 0; t < kT; t++)
                if (m & (1u << t)) a3[t] += w;
        }
        float v = 0.0f; int cnt = 0; float bbv = b3[o];
        #pragma unroll
        for (int t = 0; t < kT; t++) {
            v = (v + a3[t]) + bbv;
            if (v >= 1.0f) { cnt++; v -= 1.0f; }
        }
        out[(row0 + rr) * kOUT + o] = ((float)cnt * (1.0f / 16.0f)) * scale[o];
    }
}

// ---------------------------------------------------------------------------
extern "C" void kernel_launch(void* const* d_in, const int* in_sizes, int n_in,
                              void* d_out, int out_size)
{
    const float* feat  = (const float*)d_in[0];
    const float* W1    = (const float*)d_in[1];
    const float* b1    = (const float*)d_in[2];
    const float* W2    = (const float*)d_in[3];
    const float* b2    = (const float*)d_in[4];
    const float* W3    = (const float*)d_in[5];
    const float* b3    = (const float*)d_in[6];
    const float* scale = (const float*)d_in[7];
    float*       out   = (float*)d_out;

    const int B = in_sizes[0] / kIN;   // 32768

    cudaFuncSetAttribute(k_main, cudaFuncAttributeMaxDynamicSharedMemorySize, DYN_SZ);

    int nprep = kIN * kH1 + kH1 * kH2;
    k_prep<<<(nprep + 255) / 256, 256>>>(W1, W2);
    k_encode<<<(unsigned)(((long long)B * kIN + 255) / 256), 256>>>(feat, B);
    k_main<<<B / 16, 512, DYN_SZ>>>(b1, b2, W3, b3, scale, out);
}